// round 13
// baseline (speedup 1.0000x reference)
#include <cuda_runtime.h>
#include <math.h>
#include <stdint.h>

#define BATCH 2
#define SQ 2048
#define NH 16
#define DK 64
#define DMODEL 1024
#define NREL 4095

__device__ float g_q[BATCH*NH*SQ*DK];
__device__ float g_k[BATCH*NH*SQ*DK];
__device__ float g_v[BATCH*NH*SQ*DK];
__device__ float g_ctx[(size_t)BATCH*SQ*DMODEL];
__device__ float g_bias[NH*NREL];
__device__ float g_hid[(size_t)BATCH*SQ*DMODEL];
__device__ float g_wqkvT[3*DMODEL*DMODEL];   // [n=3072][k=1024], tf32-rounded
__device__ float g_woT[DMODEL*DMODEL];       // [n=1024][k=1024], tf32-rounded

// ---------------------------------------------------------------------------
__device__ __forceinline__ float f2tf32(float x) {
    unsigned r;
    asm("cvt.rna.tf32.f32 %0, %1;" : "=r"(r) : "f"(x));
    return __uint_as_float(r);
}

__device__ __forceinline__ void mma_tf32(float c[4], const unsigned* a,
                                         const unsigned* b) {
    asm volatile(
        "mma.sync.aligned.m16n8k8.row.col.f32.tf32.tf32.f32 "
        "{%0,%1,%2,%3}, {%4,%5,%6,%7}, {%8,%9}, {%0,%1,%2,%3};\n"
        : "+f"(c[0]), "+f"(c[1]), "+f"(c[2]), "+f"(c[3])
        : "r"(a[0]), "r"(a[1]), "r"(a[2]), "r"(a[3]), "r"(b[0]), "r"(b[1]));
}

__device__ __forceinline__ uint32_t s2u(const void* p) {
    uint32_t a;
    asm("{ .reg .u64 t; cvta.to.shared.u64 t, %1; cvt.u32.u64 %0, t; }"
        : "=r"(a) : "l"(p));
    return a;
}

// ldmatrix x4 on 32-bit data: each 8x8 b16 matrix = 8x4 f32 tile; thread t
// holds f32 at (row t>>2, col t&3) of its matrix.
__device__ __forceinline__ void ldsm4(unsigned* r, uint32_t addr) {
    asm volatile(
        "ldmatrix.sync.aligned.m8n8.x4.shared.b16 {%0,%1,%2,%3}, [%4];"
        : "=r"(r[0]), "=r"(r[1]), "=r"(r[2]), "=r"(r[3]) : "r"(addr));
}

// ---------------------------------------------------------------------------
__global__ void bias_kernel(const float* __restrict__ emb) {
    int idx = blockIdx.x * blockDim.x + threadIdx.x;
    if (idx >= NREL) return;
    int rel = idx - (SQ - 1);
    int bucket = (rel > 0) ? 16 : 0;
    int rp = rel < 0 ? -rel : rel;
    int add;
    if (rp < 8) {
        add = rp;
    } else {
        float t = logf((float)rp * 0.125f);
        float u = t / 2.772588722239781f;
        float v = u * 8.0f;
        int w = 8 + (int)v;
        add = w < 15 ? w : 15;
    }
    bucket += add;
#pragma unroll
    for (int h = 0; h < NH; h++)
        g_bias[h * NREL + idx] = emb[bucket * NH + h];
}

// Round hidden to tf32 (dst selected device-side).
__global__ void round_hid(const float* __restrict__ src) {
    size_t idx = (size_t)blockIdx.x * blockDim.x + threadIdx.x;
    float4 v = *(const float4*)(src + idx * 4);
    v.x = f2tf32(v.x); v.y = f2tf32(v.y); v.z = f2tf32(v.z); v.w = f2tf32(v.w);
    *(float4*)(g_hid + idx * 4) = v;
}

// Transpose W[k=1024][n=NCOLS] -> WT[n][k=1024], tf32-rounded.
template <int WHICH, int NCOLS>
__global__ void prep_w(const float* __restrict__ W) {
    float* WT = (WHICH == 0) ? g_wqkvT : g_woT;
    __shared__ float t[32][33];
    int bx = blockIdx.x * 32, by = blockIdx.y * 32;
    int tx = threadIdx.x, ty = threadIdx.y;
#pragma unroll
    for (int j = 0; j < 4; j++)
        t[ty + 8 * j][tx] = f2tf32(W[(size_t)(by + ty + 8 * j) * NCOLS + bx + tx]);
    __syncthreads();
#pragma unroll
    for (int j = 0; j < 4; j++)
        WT[(size_t)(bx + ty + 8 * j) * 1024 + by + tx] = t[tx][ty + 8 * j];
}

// ---------------------------------------------------------------------------
// TF32 GEMM: C[4096, NOUT] = A[4096,1024] @ BT[NOUT,1024]^T
// A and B both [row][k] in SMEM (pitch 20), fragments via ldmatrix.
// CTA 128x128, BK=16, 256 thr, 8 warps (2x4), warp tile 64x32.
// ---------------------------------------------------------------------------
#define AP 20

template <int NOUT, int MODE>
__global__ __launch_bounds__(256)
void gemm_tc(float* __restrict__ Cout) {
    __shared__ __align__(16) float As[2][128 * AP];
    __shared__ __align__(16) float Bs[2][128 * AP];

    const int n0 = blockIdx.x * 128;
    const int m0 = blockIdx.y * 128;
    const int tid = threadIdx.x;
    const int warp = tid >> 5, lane = tid & 31;
    const int wy = warp >> 2, wx = warp & 3;
    const int lr = lane >> 2, lc = lane & 3;

    // ldmatrix lane geometry
    const int a_lrow = (lane & 7) + ((lane >> 3) & 1) * 8;
    const int a_lcol = ((lane >> 4) & 1) * 4;
    const int b_lrow = (lane & 7) + ((lane >> 4) & 1) * 8;
    const int b_lcol = ((lane >> 3) & 1) * 4;
    const uint32_t sbA0 = s2u(As[0]), sbA1 = s2u(As[1]);
    const uint32_t sbB0 = s2u(Bs[0]), sbB1 = s2u(Bs[1]);

    const float* Ap = ((MODE == 0) ? g_hid : (const float*)g_ctx) + (size_t)m0 * 1024;
    const float* Bp = ((MODE == 0) ? g_wqkvT : g_woT) + (size_t)n0 * 1024;

    // Loaders: chunks fa = 2*tid, 2*tid+1; row = fa>>2 (0..127), col4 = (fa&3)*4
    const int fa = 2 * tid;
    const int row0 = fa >> 2,       c0 = (fa & 3) * 4;
    const int row1 = (fa + 1) >> 2, c1 = ((fa + 1) & 3) * 4;

    float acc[4][4][4];
#pragma unroll
    for (int i = 0; i < 4; i++)
#pragma unroll
        for (int j = 0; j < 4; j++)
#pragma unroll
            for (int r = 0; r < 4; r++) acc[i][j][r] = 0.f;

    float4 pa0, pa1, pb0, pb1;
    pa0 = *(const float4*)(Ap + (size_t)row0 * 1024 + c0);
    pa1 = *(const float4*)(Ap + (size_t)row1 * 1024 + c1);
    pb0 = *(const float4*)(Bp + (size_t)row0 * 1024 + c0);
    pb1 = *(const float4*)(Bp + (size_t)row1 * 1024 + c1);

#define STORE_STAGE(st)                                   \
    do {                                                  \
        *(float4*)(&As[st][row0 * AP + c0]) = pa0;        \
        *(float4*)(&As[st][row1 * AP + c1]) = pa1;        \
        *(float4*)(&Bs[st][row0 * AP + c0]) = pb0;        \
        *(float4*)(&Bs[st][row1 * AP + c1]) = pb1;        \
    } while (0)

    STORE_STAGE(0);
    int s = 0;

    for (int k0 = 0; k0 < 1024; k0 += 16) {
        __syncthreads();
        const bool more = (k0 + 16 < 1024);
        if (more) {
            pa0 = *(const float4*)(Ap + (size_t)row0 * 1024 + k0 + 16 + c0);
            pa1 = *(const float4*)(Ap + (size_t)row1 * 1024 + k0 + 16 + c1);
            pb0 = *(const float4*)(Bp + (size_t)row0 * 1024 + k0 + 16 + c0);
            pb1 = *(const float4*)(Bp + (size_t)row1 * 1024 + k0 + 16 + c1);
        }
        const uint32_t asb = s ? sbA1 : sbA0;
        const uint32_t bsb = s ? sbB1 : sbB0;
#pragma unroll
        for (int ks = 0; ks < 2; ks++) {
            unsigned af[4][4], bf[2][4];
#pragma unroll
            for (int mt = 0; mt < 4; mt++)
                ldsm4(af[mt], asb + (uint32_t)((wy * 64 + mt * 16 + a_lrow) * AP
                                              + ks * 8 + a_lcol) * 4u);
#pragma unroll
            for (int p = 0; p < 2; p++)
                ldsm4(bf[p], bsb + (uint32_t)((wx * 32 + p * 16 + b_lrow) * AP
                                              + ks * 8 + b_lcol) * 4u);
#pragma unroll
            for (int mt = 0; mt < 4; mt++)
#pragma unroll
                for (int p = 0; p < 2; p++) {
                    mma_tf32(acc[mt][2 * p + 0], af[mt], &bf[p][0]);
                    mma_tf32(acc[mt][2 * p + 1], af[mt], &bf[p][2]);
                }
        }
        if (more) STORE_STAGE(s ^ 1);
        s ^= 1;
    }
#undef STORE_STAGE

#pragma unroll
    for (int mt = 0; mt < 4; mt++) {
        int gm0 = m0 + wy * 64 + mt * 16 + lr;
#pragma unroll
        for (int nt = 0; nt < 4; nt++) {
            int gn = n0 + wx * 32 + nt * 8 + 2 * lc;
            if (MODE == 1) {
                *(float2*)(Cout + (size_t)gm0 * NOUT + gn) =
                    make_float2(acc[mt][nt][0], acc[mt][nt][1]);
                *(float2*)(Cout + (size_t)(gm0 + 8) * NOUT + gn) =
                    make_float2(acc[mt][nt][2], acc[mt][nt][3]);
            } else {
                const int part = gn >> 10;
                const int h = (gn & 1023) >> 6;
                const int d = gn & 63;
                float* dst = (part == 0) ? g_q : (part == 1) ? g_k : g_v;
                {
                    int b = gm0 >> 11, sq = gm0 & 2047;
                    float* row = dst + ((size_t)((b * NH + h) * SQ) + sq) * DK;
                    *(float2*)(row + d) = make_float2(acc[mt][nt][0], acc[mt][nt][1]);
                }
                {
                    int gm1 = gm0 + 8;
                    int b = gm1 >> 11, sq = gm1 & 2047;
                    float* row = dst + ((size_t)((b * NH + h) * SQ) + sq) * DK;
                    *(float2*)(row + d) = make_float2(acc[mt][nt][2], acc[mt][nt][3]);
                }
            }
        }
    }
}

// ---------------------------------------------------------------------------
// Flash attention (R11 body); finalize rounds ctx to tf32 so the MODE-1
// GEMM can copy it raw.
// ---------------------------------------------------------------------------
#define BQ 128
#define BKV 64
#define QP 68
#define KP 68
#define VP 72

__global__ __launch_bounds__(256)
void attn_tc(const float* __restrict__ mask) {
    extern __shared__ float sm[];
    float* Qs  = sm;
    float* Ks  = Qs + BQ * QP;
    float* Vs  = Ks + BKV * KP;
    float* Bsm = Vs + BKV * VP;

    const int q0 = blockIdx.x * BQ;
    const int h  = blockIdx.y;
    const int b  = blockIdx.z;
    const int tid = threadIdx.x;
    const int warp = tid >> 5, lane = tid & 31;
    const int lr = lane >> 2, lc = lane & 3;
    const int r0 = warp * 16 + lr;
    const int r1 = r0 + 8;

    const int a_lrow = (lane & 7) + ((lane >> 3) & 1) * 8;
    const int a_lcol = ((lane >> 4) & 1) * 4;
    const int k_lrow = (lane & 7) + ((lane >> 4) & 1) * 8;
    const int k_lcol = ((lane >> 3) & 1) * 4;
    const uint32_t sbQ = s2u(Qs);
    const uint32_t sbK = s2u(Ks);

    const float* Qg = g_q + ((size_t)(b * NH + h) * SQ + q0) * DK;
    const float* Kg = g_k + (size_t)(b * NH + h) * SQ * DK;
    const float* Vg = g_v + (size_t)(b * NH + h) * SQ * DK;
    const float* Mg = mask + (size_t)b * SQ * SQ;
    const float* Bg = g_bias + h * NREL;

#pragma unroll
    for (int t = 0; t < 8; t++) {
        int f = tid + t * 256;
        int r = f >> 4, c4 = (f & 15) * 4;
        float4 v = *(const float4*)(Qg + r * DK + c4);
        Qs[r * QP + c4 + 0] = f2tf32(v.x);
        Qs[r * QP + c4 + 1] = f2tf32(v.y);
        Qs[r * QP + c4 + 2] = f2tf32(v.z);
        Qs[r * QP + c4 + 3] = f2tf32(v.w);
    }

    float m0 = -3.0e38f, m1 = -3.0e38f, l0 = 0.f, l1 = 0.f;
    float o[8][4];
#pragma unroll
    for (int nt = 0; nt < 8; nt++)
#pragma unroll
        for (int r = 0; r < 4; r++) o[nt][r] = 0.f;

    const unsigned FULL = 0xffffffffu;
    const int src0 = (lane & 28) | (lc >> 1);
    const int src1 = src0 + 2;
    const bool odd = (lc & 1) != 0;

    for (int k0 = 0; k0 < SQ; k0 += BKV) {
        __syncthreads();
#pragma unroll
        for (int t = 0; t < 4; t++) {
            int f = tid + t * 256;
            int r = f >> 4, c4 = (f & 15) * 4;
            float4 kv = *(const float4*)(Kg + (size_t)(k0 + r) * DK + c4);
            Ks[r * KP + c4 + 0] = f2tf32(kv.x);
            Ks[r * KP + c4 + 1] = f2tf32(kv.y);
            Ks[r * KP + c4 + 2] = f2tf32(kv.z);
            Ks[r * KP + c4 + 3] = f2tf32(kv.w);
            float4 vv = *(const float4*)(Vg + (size_t)(k0 + r) * DK + c4);
            Vs[r * VP + c4 + 0] = f2tf32(vv.x);
            Vs[r * VP + c4 + 1] = f2tf32(vv.y);
            Vs[r * VP + c4 + 2] = f2tf32(vv.z);
            Vs[r * VP + c4 + 3] = f2tf32(vv.w);
        }
        if (tid < 191)
            Bsm[tid] = Bg[k0 - q0 + tid - 127 + (SQ - 1)];
        __syncthreads();

        float sc[8][4];
#pragma unroll
        for (int nt = 0; nt < 8; nt++)
#pragma unroll
            for (int r = 0; r < 4; r++) sc[nt][r] = 0.f;

#pragma unroll
        for (int ks = 0; ks < 8; ks++) {
            unsigned af[4], kf[4][4];
            ldsm4(af, sbQ + (uint32_t)((warp * 16 + a_lrow) * QP
                                       + ks * 8 + a_lcol) * 4u);
#pragma unroll
            for (int p = 0; p < 4; p++)
                ldsm4(kf[p], sbK + (uint32_t)((p * 16 + k_lrow) * KP
                                              + ks * 8 + k_lcol) * 4u);
#pragma unroll
            for (int p = 0; p < 4; p++) {
                mma_tf32(sc[2 * p + 0], af, &kf[p][0]);
                mma_tf32(sc[2 * p + 1], af, &kf[p][2]);
            }
        }

        {
            int gq0 = q0 + r0, gq1 = q0 + r1;
#pragma unroll
            for (int nt = 0; nt < 8; nt++) {
                int col = nt * 8 + 2 * lc;
                int kg = k0 + col;
                float2 mv0 = *(const float2*)(Mg + (size_t)gq0 * SQ + kg);
                float2 mv1 = *(const float2*)(Mg + (size_t)gq1 * SQ + kg);
                float b00 = Bsm[col - r0 + 127];
                float b01 = Bsm[col + 1 - r0 + 127];
                float b10 = Bsm[col - r1 + 127];
                float b11 = Bsm[col + 1 - r1 + 127];
                sc[nt][0] = sc[nt][0] * 0.125f * mv0.x + (b00 - 10000.f * (1.f - mv0.x));
                sc[nt][1] = sc[nt][1] * 0.125f * mv0.y + (b01 - 10000.f * (1.f - mv0.y));
                sc[nt][2] = sc[nt][2] * 0.125f * mv1.x + (b10 - 10000.f * (1.f - mv1.x));
                sc[nt][3] = sc[nt][3] * 0.125f * mv1.y + (b11 - 10000.f * (1.f - mv1.y));
            }
        }

        float tm0 = -3.0e38f, tm1 = -3.0e38f;
#pragma unroll
        for (int nt = 0; nt < 8; nt++) {
            tm0 = fmaxf(tm0, fmaxf(sc[nt][0], sc[nt][1]));
            tm1 = fmaxf(tm1, fmaxf(sc[nt][2], sc[nt][3]));
        }
        tm0 = fmaxf(tm0, __shfl_xor_sync(FULL, tm0, 1));
        tm0 = fmaxf(tm0, __shfl_xor_sync(FULL, tm0, 2));
        tm1 = fmaxf(tm1, __shfl_xor_sync(FULL, tm1, 1));
        tm1 = fmaxf(tm1, __shfl_xor_sync(FULL, tm1, 2));
        float mn0 = fmaxf(m0, tm0), mn1 = fmaxf(m1, tm1);
        float al0 = __expf(m0 - mn0), al1 = __expf(m1 - mn1);
        m0 = mn0; m1 = mn1;
        float ps0 = 0.f, ps1 = 0.f;
#pragma unroll
        for (int nt = 0; nt < 8; nt++) {
            float e0 = __expf(sc[nt][0] - mn0);
            float e1 = __expf(sc[nt][1] - mn0);
            float e2 = __expf(sc[nt][2] - mn1);
            float e3 = __expf(sc[nt][3] - mn1);
            ps0 += e0 + e1; ps1 += e2 + e3;
            sc[nt][0] = f2tf32(e0); sc[nt][1] = f2tf32(e1);
            sc[nt][2] = f2tf32(e2); sc[nt][3] = f2tf32(e3);
        }
        ps0 += __shfl_xor_sync(FULL, ps0, 1);
        ps0 += __shfl_xor_sync(FULL, ps0, 2);
        ps1 += __shfl_xor_sync(FULL, ps1, 1);
        ps1 += __shfl_xor_sync(FULL, ps1, 2);
        l0 = l0 * al0 + ps0;
        l1 = l1 * al1 + ps1;

#pragma unroll
        for (int nt = 0; nt < 8; nt++) {
            o[nt][0] *= al0; o[nt][1] *= al0;
            o[nt][2] *= al1; o[nt][3] *= al1;
        }

#pragma unroll
        for (int ks = 0; ks < 8; ks++) {
            float t00 = __shfl_sync(FULL, sc[ks][0], src0);
            float t01 = __shfl_sync(FULL, sc[ks][1], src0);
            float t10 = __shfl_sync(FULL, sc[ks][2], src0);
            float t11 = __shfl_sync(FULL, sc[ks][3], src0);
            float u00 = __shfl_sync(FULL, sc[ks][0], src1);
            float u01 = __shfl_sync(FULL, sc[ks][1], src1);
            float u10 = __shfl_sync(FULL, sc[ks][2], src1);
            float u11 = __shfl_sync(FULL, sc[ks][3], src1);
            unsigned af[4];
            af[0] = __float_as_uint(odd ? t01 : t00);
            af[1] = __float_as_uint(odd ? t11 : t10);
            af[2] = __float_as_uint(odd ? u01 : u00);
            af[3] = __float_as_uint(odd ? u11 : u10);
#pragma unroll
            for (int nt = 0; nt < 8; nt++) {
                int d = nt * 8 + lr;
                unsigned bf[2];
                bf[0] = __float_as_uint(Vs[(ks * 8 + lc) * VP + d]);
                bf[1] = __float_as_uint(Vs[(ks * 8 + lc + 4) * VP + d]);
                mma_tf32(o[nt], af, bf);
            }
        }
    }

    // Finalize: tf32-rounded ctx (raw-copied by the MODE-1 GEMM)
    {
        float li0 = 1.0f / l0, li1 = 1.0f / l1;
        int gq0 = q0 + r0, gq1 = q0 + r1;
#pragma unroll
        for (int nt = 0; nt < 8; nt++) {
            int d = h * DK + nt * 8 + 2 * lc;
            *(float2*)(g_ctx + (size_t)(b * SQ + gq0) * DMODEL + d) =
                make_float2(f2tf32(o[nt][0] * li0), f2tf32(o[nt][1] * li0));
            *(float2*)(g_ctx + (size_t)(b * SQ + gq1) * DMODEL + d) =
                make_float2(f2tf32(o[nt][2] * li1), f2tf32(o[nt][3] * li1));
        }
    }
}

// ---------------------------------------------------------------------------
extern "C" void kernel_launch(void* const* d_in, const int* in_sizes, int n_in,
                              void* d_out, int out_size) {
    (void)in_sizes; (void)n_in; (void)out_size;
    const float* hidden = (const float*)d_in[0];
    const float* mask   = (const float*)d_in[1];
    const float* Wqkv   = (const float*)d_in[2];
    const float* Wo     = (const float*)d_in[3];
    const float* emb    = (const float*)d_in[4];
    float* out = (float*)d_out;

    bias_kernel<<<16, 256>>>(emb);
    round_hid<<<4096, 256>>>(hidden);
    prep_w<0, 3072><<<dim3(96, 32), dim3(32, 8)>>>(Wqkv);
    prep_w<1, 1024><<<dim3(32, 32), dim3(32, 8)>>>(Wo);

    gemm_tc<3072, 0><<<dim3(24, 32), 256>>>(nullptr);

    const int smem_bytes = (BQ * QP + BKV * KP + BKV * VP + 192) * 4;
    cudaFuncSetAttribute(attn_tc, cudaFuncAttributeMaxDynamicSharedMemorySize,
                         smem_bytes);
    attn_tc<<<dim3(SQ / BQ, NH, BATCH), 256, smem_bytes>>>(mask);

    gemm_tc<1024, 1><<<dim3(8, 32), 256>>>(out);
}

// round 15
// speedup vs baseline: 1.0307x; 1.0307x over previous
#include <cuda_runtime.h>
#include <math.h>
#include <stdint.h>

#define BATCH 2
#define SQ 2048
#define NH 16
#define DK 64
#define DMODEL 1024
#define NREL 4095

__device__ float g_q[BATCH*NH*SQ*DK];
__device__ float g_k[BATCH*NH*SQ*DK];
__device__ float g_v[BATCH*NH*SQ*DK];
__device__ float g_ctx[(size_t)BATCH*SQ*DMODEL];
__device__ float g_bias[NH*NREL];

// ---------------------------------------------------------------------------
__device__ __forceinline__ float f2tf32(float x) {
    unsigned r;
    asm("cvt.rna.tf32.f32 %0, %1;" : "=r"(r) : "f"(x));
    return __uint_as_float(r);
}

__device__ __forceinline__ void mma_tf32(float c[4], const unsigned* a,
                                         const unsigned* b) {
    asm volatile(
        "mma.sync.aligned.m16n8k8.row.col.f32.tf32.tf32.f32 "
        "{%0,%1,%2,%3}, {%4,%5,%6,%7}, {%8,%9}, {%0,%1,%2,%3};\n"
        : "+f"(c[0]), "+f"(c[1]), "+f"(c[2]), "+f"(c[3])
        : "r"(a[0]), "r"(a[1]), "r"(a[2]), "r"(a[3]), "r"(b[0]), "r"(b[1]));
}

__device__ __forceinline__ uint32_t s2u(const void* p) {
    uint32_t a;
    asm("{ .reg .u64 t; cvta.to.shared.u64 t, %1; cvt.u32.u64 %0, t; }"
        : "=r"(a) : "l"(p));
    return a;
}

// ldmatrix x4 on 32-bit data: each 8x8 b16 matrix = 8x4 f32 tile; thread t
// holds f32 at (row t>>2, col t&3) of its matrix.
__device__ __forceinline__ void ldsm4(unsigned* r, uint32_t addr) {
    asm volatile(
        "ldmatrix.sync.aligned.m8n8.x4.shared.b16 {%0,%1,%2,%3}, [%4];"
        : "=r"(r[0]), "=r"(r[1]), "=r"(r[2]), "=r"(r[3]) : "r"(addr));
}

// ---------------------------------------------------------------------------
__global__ void bias_kernel(const float* __restrict__ emb) {
    int idx = blockIdx.x * blockDim.x + threadIdx.x;
    if (idx >= NREL) return;
    int rel = idx - (SQ - 1);
    int bucket = (rel > 0) ? 16 : 0;
    int rp = rel < 0 ? -rel : rel;
    int add;
    if (rp < 8) {
        add = rp;
    } else {
        float t = logf((float)rp * 0.125f);
        float u = t / 2.772588722239781f;
        float v = u * 8.0f;
        int w = 8 + (int)v;
        add = w < 15 ? w : 15;
    }
    bucket += add;
#pragma unroll
    for (int h = 0; h < NH; h++)
        g_bias[h * NREL + idx] = emb[bucket * NH + h];
}

// ---------------------------------------------------------------------------
// TF32 GEMM (R11 body); MODE 0 epilogue rounds q/k/v to tf32 so the
// attention loader can copy them raw (identical bits either way).
// ---------------------------------------------------------------------------
#define AP 20
#define BP 136

template <int NSZ, int MODE>
__global__ __launch_bounds__(256)
void gemm_tc(const float* __restrict__ A, const float* __restrict__ B,
             float* __restrict__ Cout) {
    __shared__ __align__(16) float As[2][128 * AP];
    __shared__ __align__(16) float Bs[2][16 * BP];

    const int n0 = blockIdx.x * 128;
    const int m0 = blockIdx.y * 128;
    const int tid = threadIdx.x;
    const int warp = tid >> 5, lane = tid & 31;
    const int wy = warp >> 2, wx = warp & 3;
    const int lr = lane >> 2, lc = lane & 3;

    // ldmatrix lane geometry for A-fragments
    const int a_lrow = (lane & 7) + ((lane >> 3) & 1) * 8;
    const int a_lcol = ((lane >> 4) & 1) * 4;
    const uint32_t sbA0 = s2u(As[0]);
    const uint32_t sbA1 = s2u(As[1]);

    const float* Abase = (MODE == 0) ? A : (const float*)g_ctx;
    const float* Ap = Abase + (size_t)m0 * 1024;
    const float* Bp = B + n0;

    const int fa = 2 * tid;
    const int a_row0 = fa >> 2,       a_c0 = (fa & 3) * 4;
    const int a_row1 = (fa + 1) >> 2, a_c1 = ((fa + 1) & 3) * 4;
    const int b_row0 = fa >> 5,       b_c0 = (fa & 31) * 4;
    const int b_row1 = (fa + 1) >> 5, b_c1 = ((fa + 1) & 31) * 4;

    float acc[4][4][4];
#pragma unroll
    for (int i = 0; i < 4; i++)
#pragma unroll
        for (int j = 0; j < 4; j++)
#pragma unroll
            for (int r = 0; r < 4; r++) acc[i][j][r] = 0.f;

    float4 pa0, pa1, pb0, pb1;
    pa0 = *(const float4*)(Ap + (size_t)a_row0 * 1024 + a_c0);
    pa1 = *(const float4*)(Ap + (size_t)a_row1 * 1024 + a_c1);
    pb0 = *(const float4*)(Bp + (size_t)b_row0 * NSZ + b_c0);
    pb1 = *(const float4*)(Bp + (size_t)b_row1 * NSZ + b_c1);

#define STORE_STAGE(st)                                   \
    do {                                                  \
        float* as = As[st]; float* bs = Bs[st];           \
        as[a_row0 * AP + a_c0 + 0] = f2tf32(pa0.x);       \
        as[a_row0 * AP + a_c0 + 1] = f2tf32(pa0.y);       \
        as[a_row0 * AP + a_c0 + 2] = f2tf32(pa0.z);       \
        as[a_row0 * AP + a_c0 + 3] = f2tf32(pa0.w);       \
        as[a_row1 * AP + a_c1 + 0] = f2tf32(pa1.x);       \
        as[a_row1 * AP + a_c1 + 1] = f2tf32(pa1.y);       \
        as[a_row1 * AP + a_c1 + 2] = f2tf32(pa1.z);       \
        as[a_row1 * AP + a_c1 + 3] = f2tf32(pa1.w);       \
        bs[b_row0 * BP + b_c0 + 0] = f2tf32(pb0.x);       \
        bs[b_row0 * BP + b_c0 + 1] = f2tf32(pb0.y);       \
        bs[b_row0 * BP + b_c0 + 2] = f2tf32(pb0.z);       \
        bs[b_row0 * BP + b_c0 + 3] = f2tf32(pb0.w);       \
        bs[b_row1 * BP + b_c1 + 0] = f2tf32(pb1.x);       \
        bs[b_row1 * BP + b_c1 + 1] = f2tf32(pb1.y);       \
        bs[b_row1 * BP + b_c1 + 2] = f2tf32(pb1.z);       \
        bs[b_row1 * BP + b_c1 + 3] = f2tf32(pb1.w);       \
    } while (0)

    STORE_STAGE(0);
    int s = 0;

    for (int k0 = 0; k0 < 1024; k0 += 16) {
        __syncthreads();
        const bool more = (k0 + 16 < 1024);
        if (more) {
            pa0 = *(const float4*)(Ap + (size_t)a_row0 * 1024 + k0 + 16 + a_c0);
            pa1 = *(const float4*)(Ap + (size_t)a_row1 * 1024 + k0 + 16 + a_c1);
            pb0 = *(const float4*)(Bp + (size_t)(k0 + 16 + b_row0) * NSZ + b_c0);
            pb1 = *(const float4*)(Bp + (size_t)(k0 + 16 + b_row1) * NSZ + b_c1);
        }
        const uint32_t asb = s ? sbA1 : sbA0;
        const float* bs = Bs[s];
#pragma unroll
        for (int ks = 0; ks < 2; ks++) {
            unsigned af[4][4], bf[4][2];
#pragma unroll
            for (int mt = 0; mt < 4; mt++)
                ldsm4(af[mt], asb + (uint32_t)((wy * 64 + mt * 16 + a_lrow) * AP
                                              + ks * 8 + a_lcol) * 4u);
#pragma unroll
            for (int nt = 0; nt < 4; nt++) {
                int n = wx * 32 + nt * 8 + lr;
                bf[nt][0] = __float_as_uint(bs[(ks * 8 + lc) * BP + n]);
                bf[nt][1] = __float_as_uint(bs[(ks * 8 + lc + 4) * BP + n]);
            }
#pragma unroll
            for (int mt = 0; mt < 4; mt++)
#pragma unroll
                for (int nt = 0; nt < 4; nt++)
                    mma_tf32(acc[mt][nt], af[mt], bf[nt]);
        }
        if (more) STORE_STAGE(s ^ 1);
        s ^= 1;
    }
#undef STORE_STAGE

#pragma unroll
    for (int mt = 0; mt < 4; mt++) {
        int gm0 = m0 + wy * 64 + mt * 16 + lr;
#pragma unroll
        for (int nt = 0; nt < 4; nt++) {
            int gn = n0 + wx * 32 + nt * 8 + 2 * lc;
            if (MODE == 1) {
                *(float2*)(Cout + (size_t)gm0 * NSZ + gn) =
                    make_float2(acc[mt][nt][0], acc[mt][nt][1]);
                *(float2*)(Cout + (size_t)(gm0 + 8) * NSZ + gn) =
                    make_float2(acc[mt][nt][2], acc[mt][nt][3]);
            } else {
                const int part = gn >> 10;
                const int h = (gn & 1023) >> 6;
                const int d = gn & 63;
                float* dst = (part == 0) ? g_q : (part == 1) ? g_k : g_v;
                {
                    int b = gm0 >> 11, sq = gm0 & 2047;
                    float* row = dst + ((size_t)((b * NH + h) * SQ) + sq) * DK;
                    *(float2*)(row + d) =
                        make_float2(f2tf32(acc[mt][nt][0]), f2tf32(acc[mt][nt][1]));
                }
                {
                    int gm1 = gm0 + 8;
                    int b = gm1 >> 11, sq = gm1 & 2047;
                    float* row = dst + ((size_t)((b * NH + h) * SQ) + sq) * DK;
                    *(float2*)(row + d) =
                        make_float2(f2tf32(acc[mt][nt][2]), f2tf32(acc[mt][nt][3]));
                }
            }
        }
    }
}

// ---------------------------------------------------------------------------
// Flash attention (R11 body); q/k/v pre-rounded -> loaders are raw
// LDG.128 -> STS.128 with zero cvt. Finalize rounds ctx (idempotent with
// the MODE-1 GEMM's own rounding).
// ---------------------------------------------------------------------------
#define BQ 128
#define BKV 64
#define QP 68
#define KP 68
#define VP 72

__global__ __launch_bounds__(256)
void attn_tc(const float* __restrict__ mask) {
    extern __shared__ float sm[];
    float* Qs  = sm;
    float* Ks  = Qs + BQ * QP;
    float* Vs  = Ks + BKV * KP;
    float* Bsm = Vs + BKV * VP;

    const int q0 = blockIdx.x * BQ;
    const int h  = blockIdx.y;
    const int b  = blockIdx.z;
    const int tid = threadIdx.x;
    const int warp = tid >> 5, lane = tid & 31;
    const int lr = lane >> 2, lc = lane & 3;
    const int r0 = warp * 16 + lr;
    const int r1 = r0 + 8;

    const int a_lrow = (lane & 7) + ((lane >> 3) & 1) * 8;
    const int a_lcol = ((lane >> 4) & 1) * 4;
    const int k_lrow = (lane & 7) + ((lane >> 4) & 1) * 8;
    const int k_lcol = ((lane >> 3) & 1) * 4;
    const uint32_t sbQ = s2u(Qs);
    const uint32_t sbK = s2u(Ks);

    const float* Qg = g_q + ((size_t)(b * NH + h) * SQ + q0) * DK;
    const float* Kg = g_k + (size_t)(b * NH + h) * SQ * DK;
    const float* Vg = g_v + (size_t)(b * NH + h) * SQ * DK;
    const float* Mg = mask + (size_t)b * SQ * SQ;
    const float* Bg = g_bias + h * NREL;

    // Q tile: raw vectorized copy (already tf32-rounded)
#pragma unroll
    for (int t = 0; t < 8; t++) {
        int f = tid + t * 256;
        int r = f >> 4, c4 = (f & 15) * 4;
        *(float4*)(&Qs[r * QP + c4]) = *(const float4*)(Qg + r * DK + c4);
    }

    float m0 = -3.0e38f, m1 = -3.0e38f, l0 = 0.f, l1 = 0.f;
    float o[8][4];
#pragma unroll
    for (int nt = 0; nt < 8; nt++)
#pragma unroll
        for (int r = 0; r < 4; r++) o[nt][r] = 0.f;

    const unsigned FULL = 0xffffffffu;
    const int src0 = (lane & 28) | (lc >> 1);
    const int src1 = src0 + 2;
    const bool odd = (lc & 1) != 0;

    for (int k0 = 0; k0 < SQ; k0 += BKV) {
        __syncthreads();
        // K/V tiles: raw vectorized copies
#pragma unroll
        for (int t = 0; t < 4; t++) {
            int f = tid + t * 256;
            int r = f >> 4, c4 = (f & 15) * 4;
            *(float4*)(&Ks[r * KP + c4]) =
                *(const float4*)(Kg + (size_t)(k0 + r) * DK + c4);
            *(float4*)(&Vs[r * VP + c4]) =
                *(const float4*)(Vg + (size_t)(k0 + r) * DK + c4);
        }
        if (tid < 191)
            Bsm[tid] = Bg[k0 - q0 + tid - 127 + (SQ - 1)];
        __syncthreads();

        float sc[8][4];
#pragma unroll
        for (int nt = 0; nt < 8; nt++)
#pragma unroll
            for (int r = 0; r < 4; r++) sc[nt][r] = 0.f;

#pragma unroll
        for (int ks = 0; ks < 8; ks++) {
            unsigned af[4], kf[4][4];
            ldsm4(af, sbQ + (uint32_t)((warp * 16 + a_lrow) * QP
                                       + ks * 8 + a_lcol) * 4u);
#pragma unroll
            for (int p = 0; p < 4; p++)
                ldsm4(kf[p], sbK + (uint32_t)((p * 16 + k_lrow) * KP
                                              + ks * 8 + k_lcol) * 4u);
#pragma unroll
            for (int p = 0; p < 4; p++) {
                mma_tf32(sc[2 * p + 0], af, &kf[p][0]);
                mma_tf32(sc[2 * p + 1], af, &kf[p][2]);
            }
        }

        {
            int gq0 = q0 + r0, gq1 = q0 + r1;
#pragma unroll
            for (int nt = 0; nt < 8; nt++) {
                int col = nt * 8 + 2 * lc;
                int kg = k0 + col;
                float2 mv0 = *(const float2*)(Mg + (size_t)gq0 * SQ + kg);
                float2 mv1 = *(const float2*)(Mg + (size_t)gq1 * SQ + kg);
                float b00 = Bsm[col - r0 + 127];
                float b01 = Bsm[col + 1 - r0 + 127];
                float b10 = Bsm[col - r1 + 127];
                float b11 = Bsm[col + 1 - r1 + 127];
                sc[nt][0] = sc[nt][0] * 0.125f * mv0.x + (b00 - 10000.f * (1.f - mv0.x));
                sc[nt][1] = sc[nt][1] * 0.125f * mv0.y + (b01 - 10000.f * (1.f - mv0.y));
                sc[nt][2] = sc[nt][2] * 0.125f * mv1.x + (b10 - 10000.f * (1.f - mv1.x));
                sc[nt][3] = sc[nt][3] * 0.125f * mv1.y + (b11 - 10000.f * (1.f - mv1.y));
            }
        }

        float tm0 = -3.0e38f, tm1 = -3.0e38f;
#pragma unroll
        for (int nt = 0; nt < 8; nt++) {
            tm0 = fmaxf(tm0, fmaxf(sc[nt][0], sc[nt][1]));
            tm1 = fmaxf(tm1, fmaxf(sc[nt][2], sc[nt][3]));
        }
        tm0 = fmaxf(tm0, __shfl_xor_sync(FULL, tm0, 1));
        tm0 = fmaxf(tm0, __shfl_xor_sync(FULL, tm0, 2));
        tm1 = fmaxf(tm1, __shfl_xor_sync(FULL, tm1, 1));
        tm1 = fmaxf(tm1, __shfl_xor_sync(FULL, tm1, 2));
        float mn0 = fmaxf(m0, tm0), mn1 = fmaxf(m1, tm1);
        float al0 = __expf(m0 - mn0), al1 = __expf(m1 - mn1);
        m0 = mn0; m1 = mn1;
        float ps0 = 0.f, ps1 = 0.f;
#pragma unroll
        for (int nt = 0; nt < 8; nt++) {
            float e0 = __expf(sc[nt][0] - mn0);
            float e1 = __expf(sc[nt][1] - mn0);
            float e2 = __expf(sc[nt][2] - mn1);
            float e3 = __expf(sc[nt][3] - mn1);
            ps0 += e0 + e1; ps1 += e2 + e3;
            sc[nt][0] = f2tf32(e0); sc[nt][1] = f2tf32(e1);
            sc[nt][2] = f2tf32(e2); sc[nt][3] = f2tf32(e3);
        }
        ps0 += __shfl_xor_sync(FULL, ps0, 1);
        ps0 += __shfl_xor_sync(FULL, ps0, 2);
        ps1 += __shfl_xor_sync(FULL, ps1, 1);
        ps1 += __shfl_xor_sync(FULL, ps1, 2);
        l0 = l0 * al0 + ps0;
        l1 = l1 * al1 + ps1;

#pragma unroll
        for (int nt = 0; nt < 8; nt++) {
            o[nt][0] *= al0; o[nt][1] *= al0;
            o[nt][2] *= al1; o[nt][3] *= al1;
        }

#pragma unroll
        for (int ks = 0; ks < 8; ks++) {
            float t00 = __shfl_sync(FULL, sc[ks][0], src0);
            float t01 = __shfl_sync(FULL, sc[ks][1], src0);
            float t10 = __shfl_sync(FULL, sc[ks][2], src0);
            float t11 = __shfl_sync(FULL, sc[ks][3], src0);
            float u00 = __shfl_sync(FULL, sc[ks][0], src1);
            float u01 = __shfl_sync(FULL, sc[ks][1], src1);
            float u10 = __shfl_sync(FULL, sc[ks][2], src1);
            float u11 = __shfl_sync(FULL, sc[ks][3], src1);
            unsigned af[4];
            af[0] = __float_as_uint(odd ? t01 : t00);
            af[1] = __float_as_uint(odd ? t11 : t10);
            af[2] = __float_as_uint(odd ? u01 : u00);
            af[3] = __float_as_uint(odd ? u11 : u10);
#pragma unroll
            for (int nt = 0; nt < 8; nt++) {
                int d = nt * 8 + lr;
                unsigned bf[2];
                bf[0] = __float_as_uint(Vs[(ks * 8 + lc) * VP + d]);
                bf[1] = __float_as_uint(Vs[(ks * 8 + lc + 4) * VP + d]);
                mma_tf32(o[nt], af, bf);
            }
        }
    }

    {
        float li0 = 1.0f / l0, li1 = 1.0f / l1;
        int gq0 = q0 + r0, gq1 = q0 + r1;
#pragma unroll
        for (int nt = 0; nt < 8; nt++) {
            int d = h * DK + nt * 8 + 2 * lc;
            *(float2*)(g_ctx + (size_t)(b * SQ + gq0) * DMODEL + d) =
                make_float2(o[nt][0] * li0, o[nt][1] * li0);
            *(float2*)(g_ctx + (size_t)(b * SQ + gq1) * DMODEL + d) =
                make_float2(o[nt][2] * li1, o[nt][3] * li1);
        }
    }
}

// ---------------------------------------------------------------------------
extern "C" void kernel_launch(void* const* d_in, const int* in_sizes, int n_in,
                              void* d_out, int out_size) {
    (void)in_sizes; (void)n_in; (void)out_size;
    const float* hidden = (const float*)d_in[0];
    const float* mask   = (const float*)d_in[1];
    const float* Wqkv   = (const float*)d_in[2];
    const float* Wo     = (const float*)d_in[3];
    const float* emb    = (const float*)d_in[4];
    float* out = (float*)d_out;

    bias_kernel<<<16, 256>>>(emb);

    gemm_tc<3072, 0><<<dim3(24, 32), 256>>>(hidden, Wqkv, nullptr);

    const int smem_bytes = (BQ * QP + BKV * KP + BKV * VP + 192) * 4;
    cudaFuncSetAttribute(attn_tc, cudaFuncAttributeMaxDynamicSharedMemorySize,
                         smem_bytes);
    attn_tc<<<dim3(SQ / BQ, NH, BATCH), 256, smem_bytes>>>(mask);

    gemm_tc<1024, 1><<<dim3(8, 32), 256>>>(nullptr, Wo, out);
}

// round 16
// speedup vs baseline: 1.1210x; 1.0877x over previous
#include <cuda_runtime.h>
#include <math.h>
#include <stdint.h>

#define BATCH 2
#define SQ 2048
#define NH 16
#define DK 64
#define DMODEL 1024
#define NREL 4095

__device__ float g_q[BATCH*NH*SQ*DK];
__device__ float g_k[BATCH*NH*SQ*DK];
__device__ float g_v[BATCH*NH*SQ*DK];
__device__ float g_ctx[(size_t)BATCH*SQ*DMODEL];
__device__ float g_bias[NH*NREL];
__device__ int   g_mask_ones;

// ---------------------------------------------------------------------------
__device__ __forceinline__ float f2tf32(float x) {
    unsigned r;
    asm("cvt.rna.tf32.f32 %0, %1;" : "=r"(r) : "f"(x));
    return __uint_as_float(r);
}

__device__ __forceinline__ void mma_tf32(float c[4], const unsigned* a,
                                         const unsigned* b) {
    asm volatile(
        "mma.sync.aligned.m16n8k8.row.col.f32.tf32.tf32.f32 "
        "{%0,%1,%2,%3}, {%4,%5,%6,%7}, {%8,%9}, {%0,%1,%2,%3};\n"
        : "+f"(c[0]), "+f"(c[1]), "+f"(c[2]), "+f"(c[3])
        : "r"(a[0]), "r"(a[1]), "r"(a[2]), "r"(a[3]), "r"(b[0]), "r"(b[1]));
}

__device__ __forceinline__ uint32_t s2u(const void* p) {
    uint32_t a;
    asm("{ .reg .u64 t; cvta.to.shared.u64 t, %1; cvt.u32.u64 %0, t; }"
        : "=r"(a) : "l"(p));
    return a;
}

__device__ __forceinline__ void ldsm4(unsigned* r, uint32_t addr) {
    asm volatile(
        "ldmatrix.sync.aligned.m8n8.x4.shared.b16 {%0,%1,%2,%3}, [%4];"
        : "=r"(r[0]), "=r"(r[1]), "=r"(r[2]), "=r"(r[3]) : "r"(addr));
}

// ---------------------------------------------------------------------------
__global__ void bias_kernel(const float* __restrict__ emb) {
    int idx = blockIdx.x * blockDim.x + threadIdx.x;
    if (idx >= NREL) return;
    int rel = idx - (SQ - 1);
    int bucket = (rel > 0) ? 16 : 0;
    int rp = rel < 0 ? -rel : rel;
    int add;
    if (rp < 8) {
        add = rp;
    } else {
        float t = logf((float)rp * 0.125f);
        float u = t / 2.772588722239781f;
        float v = u * 8.0f;
        int w = 8 + (int)v;
        add = w < 15 ? w : 15;
    }
    bucket += add;
#pragma unroll
    for (int h = 0; h < NH; h++)
        g_bias[h * NREL + idx] = emb[bucket * NH + h];
}

__global__ void flag_init_kernel() { g_mask_ones = 1; }

// Check whether the mask is all ones (8.4M floats = 2097152 float4).
__global__ void mask_check_kernel(const float* __restrict__ mask) {
    size_t t = (size_t)blockIdx.x * blockDim.x + threadIdx.x;
    const float4* p = (const float4*)mask + t * 4;
    bool ok = true;
#pragma unroll
    for (int i = 0; i < 4; i++) {
        float4 v = p[i];
        ok &= (v.x == 1.0f) & (v.y == 1.0f) & (v.z == 1.0f) & (v.w == 1.0f);
    }
    if (!__all_sync(0xffffffffu, ok)) {
        if ((threadIdx.x & 31) == 0) atomicExch(&g_mask_ones, 0);
    }
}

// ---------------------------------------------------------------------------
// TF32 GEMM (R14 body, unchanged).
// ---------------------------------------------------------------------------
#define AP 20
#define BP 136

template <int NSZ, int MODE>
__global__ __launch_bounds__(256)
void gemm_tc(const float* __restrict__ A, const float* __restrict__ B,
             float* __restrict__ Cout) {
    __shared__ __align__(16) float As[2][128 * AP];
    __shared__ __align__(16) float Bs[2][16 * BP];

    const int n0 = blockIdx.x * 128;
    const int m0 = blockIdx.y * 128;
    const int tid = threadIdx.x;
    const int warp = tid >> 5, lane = tid & 31;
    const int wy = warp >> 2, wx = warp & 3;
    const int lr = lane >> 2, lc = lane & 3;

    const int a_lrow = (lane & 7) + ((lane >> 3) & 1) * 8;
    const int a_lcol = ((lane >> 4) & 1) * 4;
    const uint32_t sbA0 = s2u(As[0]);
    const uint32_t sbA1 = s2u(As[1]);

    const float* Abase = (MODE == 0) ? A : (const float*)g_ctx;
    const float* Ap = Abase + (size_t)m0 * 1024;
    const float* Bp = B + n0;

    const int fa = 2 * tid;
    const int a_row0 = fa >> 2,       a_c0 = (fa & 3) * 4;
    const int a_row1 = (fa + 1) >> 2, a_c1 = ((fa + 1) & 3) * 4;
    const int b_row0 = fa >> 5,       b_c0 = (fa & 31) * 4;
    const int b_row1 = (fa + 1) >> 5, b_c1 = ((fa + 1) & 31) * 4;

    float acc[4][4][4];
#pragma unroll
    for (int i = 0; i < 4; i++)
#pragma unroll
        for (int j = 0; j < 4; j++)
#pragma unroll
            for (int r = 0; r < 4; r++) acc[i][j][r] = 0.f;

    float4 pa0, pa1, pb0, pb1;
    pa0 = *(const float4*)(Ap + (size_t)a_row0 * 1024 + a_c0);
    pa1 = *(const float4*)(Ap + (size_t)a_row1 * 1024 + a_c1);
    pb0 = *(const float4*)(Bp + (size_t)b_row0 * NSZ + b_c0);
    pb1 = *(const float4*)(Bp + (size_t)b_row1 * NSZ + b_c1);

#define STORE_STAGE(st)                                   \
    do {                                                  \
        float* as = As[st]; float* bs = Bs[st];           \
        as[a_row0 * AP + a_c0 + 0] = f2tf32(pa0.x);       \
        as[a_row0 * AP + a_c0 + 1] = f2tf32(pa0.y);       \
        as[a_row0 * AP + a_c0 + 2] = f2tf32(pa0.z);       \
        as[a_row0 * AP + a_c0 + 3] = f2tf32(pa0.w);       \
        as[a_row1 * AP + a_c1 + 0] = f2tf32(pa1.x);       \
        as[a_row1 * AP + a_c1 + 1] = f2tf32(pa1.y);       \
        as[a_row1 * AP + a_c1 + 2] = f2tf32(pa1.z);       \
        as[a_row1 * AP + a_c1 + 3] = f2tf32(pa1.w);       \
        bs[b_row0 * BP + b_c0 + 0] = f2tf32(pb0.x);       \
        bs[b_row0 * BP + b_c0 + 1] = f2tf32(pb0.y);       \
        bs[b_row0 * BP + b_c0 + 2] = f2tf32(pb0.z);       \
        bs[b_row0 * BP + b_c0 + 3] = f2tf32(pb0.w);       \
        bs[b_row1 * BP + b_c1 + 0] = f2tf32(pb1.x);       \
        bs[b_row1 * BP + b_c1 + 1] = f2tf32(pb1.y);       \
        bs[b_row1 * BP + b_c1 + 2] = f2tf32(pb1.z);       \
        bs[b_row1 * BP + b_c1 + 3] = f2tf32(pb1.w);       \
    } while (0)

    STORE_STAGE(0);
    int s = 0;

    for (int k0 = 0; k0 < 1024; k0 += 16) {
        __syncthreads();
        const bool more = (k0 + 16 < 1024);
        if (more) {
            pa0 = *(const float4*)(Ap + (size_t)a_row0 * 1024 + k0 + 16 + a_c0);
            pa1 = *(const float4*)(Ap + (size_t)a_row1 * 1024 + k0 + 16 + a_c1);
            pb0 = *(const float4*)(Bp + (size_t)(k0 + 16 + b_row0) * NSZ + b_c0);
            pb1 = *(const float4*)(Bp + (size_t)(k0 + 16 + b_row1) * NSZ + b_c1);
        }
        const uint32_t asb = s ? sbA1 : sbA0;
        const float* bs = Bs[s];
#pragma unroll
        for (int ks = 0; ks < 2; ks++) {
            unsigned af[4][4], bf[4][2];
#pragma unroll
            for (int mt = 0; mt < 4; mt++)
                ldsm4(af[mt], asb + (uint32_t)((wy * 64 + mt * 16 + a_lrow) * AP
                                              + ks * 8 + a_lcol) * 4u);
#pragma unroll
            for (int nt = 0; nt < 4; nt++) {
                int n = wx * 32 + nt * 8 + lr;
                bf[nt][0] = __float_as_uint(bs[(ks * 8 + lc) * BP + n]);
                bf[nt][1] = __float_as_uint(bs[(ks * 8 + lc + 4) * BP + n]);
            }
#pragma unroll
            for (int mt = 0; mt < 4; mt++)
#pragma unroll
                for (int nt = 0; nt < 4; nt++)
                    mma_tf32(acc[mt][nt], af[mt], bf[nt]);
        }
        if (more) STORE_STAGE(s ^ 1);
        s ^= 1;
    }
#undef STORE_STAGE

#pragma unroll
    for (int mt = 0; mt < 4; mt++) {
        int gm0 = m0 + wy * 64 + mt * 16 + lr;
#pragma unroll
        for (int nt = 0; nt < 4; nt++) {
            int gn = n0 + wx * 32 + nt * 8 + 2 * lc;
            if (MODE == 1) {
                *(float2*)(Cout + (size_t)gm0 * NSZ + gn) =
                    make_float2(acc[mt][nt][0], acc[mt][nt][1]);
                *(float2*)(Cout + (size_t)(gm0 + 8) * NSZ + gn) =
                    make_float2(acc[mt][nt][2], acc[mt][nt][3]);
            } else {
                const int part = gn >> 10;
                const int h = (gn & 1023) >> 6;
                const int d = gn & 63;
                float* dst = (part == 0) ? g_q : (part == 1) ? g_k : g_v;
                {
                    int b = gm0 >> 11, sq = gm0 & 2047;
                    float* row = dst + ((size_t)((b * NH + h) * SQ) + sq) * DK;
                    *(float2*)(row + d) =
                        make_float2(f2tf32(acc[mt][nt][0]), f2tf32(acc[mt][nt][1]));
                }
                {
                    int gm1 = gm0 + 8;
                    int b = gm1 >> 11, sq = gm1 & 2047;
                    float* row = dst + ((size_t)((b * NH + h) * SQ) + sq) * DK;
                    *(float2*)(row + d) =
                        make_float2(f2tf32(acc[mt][nt][2]), f2tf32(acc[mt][nt][3]));
                }
            }
        }
    }
}

// ---------------------------------------------------------------------------
// Flash attention (R14 body) + all-ones mask fast path.
// ---------------------------------------------------------------------------
#define BQ 128
#define BKV 64
#define QP 68
#define KP 68
#define VP 72

__global__ __launch_bounds__(256)
void attn_tc(const float* __restrict__ mask) {
    extern __shared__ float sm[];
    float* Qs  = sm;
    float* Ks  = Qs + BQ * QP;
    float* Vs  = Ks + BKV * KP;
    float* Bsm = Vs + BKV * VP;

    const int q0 = blockIdx.x * BQ;
    const int h  = blockIdx.y;
    const int b  = blockIdx.z;
    const int tid = threadIdx.x;
    const int warp = tid >> 5, lane = tid & 31;
    const int lr = lane >> 2, lc = lane & 3;
    const int r0 = warp * 16 + lr;
    const int r1 = r0 + 8;

    const int a_lrow = (lane & 7) + ((lane >> 3) & 1) * 8;
    const int a_lcol = ((lane >> 4) & 1) * 4;
    const int k_lrow = (lane & 7) + ((lane >> 4) & 1) * 8;
    const int k_lcol = ((lane >> 3) & 1) * 4;
    const uint32_t sbQ = s2u(Qs);
    const uint32_t sbK = s2u(Ks);

    const float* Qg = g_q + ((size_t)(b * NH + h) * SQ + q0) * DK;
    const float* Kg = g_k + (size_t)(b * NH + h) * SQ * DK;
    const float* Vg = g_v + (size_t)(b * NH + h) * SQ * DK;
    const float* Mg = mask + (size_t)b * SQ * SQ;
    const float* Bg = g_bias + h * NREL;

    const bool mask_ones = (g_mask_ones != 0);

#pragma unroll
    for (int t = 0; t < 8; t++) {
        int f = tid + t * 256;
        int r = f >> 4, c4 = (f & 15) * 4;
        *(float4*)(&Qs[r * QP + c4]) = *(const float4*)(Qg + r * DK + c4);
    }

    float m0 = -3.0e38f, m1 = -3.0e38f, l0 = 0.f, l1 = 0.f;
    float o[8][4];
#pragma unroll
    for (int nt = 0; nt < 8; nt++)
#pragma unroll
        for (int r = 0; r < 4; r++) o[nt][r] = 0.f;

    const unsigned FULL = 0xffffffffu;
    const int src0 = (lane & 28) | (lc >> 1);
    const int src1 = src0 + 2;
    const bool odd = (lc & 1) != 0;

    for (int k0 = 0; k0 < SQ; k0 += BKV) {
        __syncthreads();
#pragma unroll
        for (int t = 0; t < 4; t++) {
            int f = tid + t * 256;
            int r = f >> 4, c4 = (f & 15) * 4;
            *(float4*)(&Ks[r * KP + c4]) =
                *(const float4*)(Kg + (size_t)(k0 + r) * DK + c4);
            *(float4*)(&Vs[r * VP + c4]) =
                *(const float4*)(Vg + (size_t)(k0 + r) * DK + c4);
        }
        if (tid < 191)
            Bsm[tid] = Bg[k0 - q0 + tid - 127 + (SQ - 1)];
        __syncthreads();

        float sc[8][4];
#pragma unroll
        for (int nt = 0; nt < 8; nt++)
#pragma unroll
            for (int r = 0; r < 4; r++) sc[nt][r] = 0.f;

#pragma unroll
        for (int ks = 0; ks < 8; ks++) {
            unsigned af[4], kf[4][4];
            ldsm4(af, sbQ + (uint32_t)((warp * 16 + a_lrow) * QP
                                       + ks * 8 + a_lcol) * 4u);
#pragma unroll
            for (int p = 0; p < 4; p++)
                ldsm4(kf[p], sbK + (uint32_t)((p * 16 + k_lrow) * KP
                                              + ks * 8 + k_lcol) * 4u);
#pragma unroll
            for (int p = 0; p < 4; p++) {
                mma_tf32(sc[2 * p + 0], af, &kf[p][0]);
                mma_tf32(sc[2 * p + 1], af, &kf[p][2]);
            }
        }

        if (mask_ones) {
            // Fast path: bit-exact reduction of the masked expression at m=1:
            // sc*0.125*1 + (b - 10000*0)  ==  RN(RN(sc*0.125) + b)
#pragma unroll
            for (int nt = 0; nt < 8; nt++) {
                int col = nt * 8 + 2 * lc;
                float b00 = Bsm[col - r0 + 127];
                float b01 = Bsm[col + 1 - r0 + 127];
                float b10 = Bsm[col - r1 + 127];
                float b11 = Bsm[col + 1 - r1 + 127];
                sc[nt][0] = __fadd_rn(__fmul_rn(sc[nt][0], 0.125f), b00);
                sc[nt][1] = __fadd_rn(__fmul_rn(sc[nt][1], 0.125f), b01);
                sc[nt][2] = __fadd_rn(__fmul_rn(sc[nt][2], 0.125f), b10);
                sc[nt][3] = __fadd_rn(__fmul_rn(sc[nt][3], 0.125f), b11);
            }
        } else {
            int gq0 = q0 + r0, gq1 = q0 + r1;
#pragma unroll
            for (int nt = 0; nt < 8; nt++) {
                int col = nt * 8 + 2 * lc;
                int kg = k0 + col;
                float2 mv0 = *(const float2*)(Mg + (size_t)gq0 * SQ + kg);
                float2 mv1 = *(const float2*)(Mg + (size_t)gq1 * SQ + kg);
                float b00 = Bsm[col - r0 + 127];
                float b01 = Bsm[col + 1 - r0 + 127];
                float b10 = Bsm[col - r1 + 127];
                float b11 = Bsm[col + 1 - r1 + 127];
                sc[nt][0] = sc[nt][0] * 0.125f * mv0.x + (b00 - 10000.f * (1.f - mv0.x));
                sc[nt][1] = sc[nt][1] * 0.125f * mv0.y + (b01 - 10000.f * (1.f - mv0.y));
                sc[nt][2] = sc[nt][2] * 0.125f * mv1.x + (b10 - 10000.f * (1.f - mv1.x));
                sc[nt][3] = sc[nt][3] * 0.125f * mv1.y + (b11 - 10000.f * (1.f - mv1.y));
            }
        }

        float tm0 = -3.0e38f, tm1 = -3.0e38f;
#pragma unroll
        for (int nt = 0; nt < 8; nt++) {
            tm0 = fmaxf(tm0, fmaxf(sc[nt][0], sc[nt][1]));
            tm1 = fmaxf(tm1, fmaxf(sc[nt][2], sc[nt][3]));
        }
        tm0 = fmaxf(tm0, __shfl_xor_sync(FULL, tm0, 1));
        tm0 = fmaxf(tm0, __shfl_xor_sync(FULL, tm0, 2));
        tm1 = fmaxf(tm1, __shfl_xor_sync(FULL, tm1, 1));
        tm1 = fmaxf(tm1, __shfl_xor_sync(FULL, tm1, 2));
        float mn0 = fmaxf(m0, tm0), mn1 = fmaxf(m1, tm1);
        float al0 = __expf(m0 - mn0), al1 = __expf(m1 - mn1);
        m0 = mn0; m1 = mn1;
        float ps0 = 0.f, ps1 = 0.f;
#pragma unroll
        for (int nt = 0; nt < 8; nt++) {
            float e0 = __expf(sc[nt][0] - mn0);
            float e1 = __expf(sc[nt][1] - mn0);
            float e2 = __expf(sc[nt][2] - mn1);
            float e3 = __expf(sc[nt][3] - mn1);
            ps0 += e0 + e1; ps1 += e2 + e3;
            sc[nt][0] = f2tf32(e0); sc[nt][1] = f2tf32(e1);
            sc[nt][2] = f2tf32(e2); sc[nt][3] = f2tf32(e3);
        }
        ps0 += __shfl_xor_sync(FULL, ps0, 1);
        ps0 += __shfl_xor_sync(FULL, ps0, 2);
        ps1 += __shfl_xor_sync(FULL, ps1, 1);
        ps1 += __shfl_xor_sync(FULL, ps1, 2);
        l0 = l0 * al0 + ps0;
        l1 = l1 * al1 + ps1;

#pragma unroll
        for (int nt = 0; nt < 8; nt++) {
            o[nt][0] *= al0; o[nt][1] *= al0;
            o[nt][2] *= al1; o[nt][3] *= al1;
        }

#pragma unroll
        for (int ks = 0; ks < 8; ks++) {
            float t00 = __shfl_sync(FULL, sc[ks][0], src0);
            float t01 = __shfl_sync(FULL, sc[ks][1], src0);
            float t10 = __shfl_sync(FULL, sc[ks][2], src0);
            float t11 = __shfl_sync(FULL, sc[ks][3], src0);
            float u00 = __shfl_sync(FULL, sc[ks][0], src1);
            float u01 = __shfl_sync(FULL, sc[ks][1], src1);
            float u10 = __shfl_sync(FULL, sc[ks][2], src1);
            float u11 = __shfl_sync(FULL, sc[ks][3], src1);
            unsigned af[4];
            af[0] = __float_as_uint(odd ? t01 : t00);
            af[1] = __float_as_uint(odd ? t11 : t10);
            af[2] = __float_as_uint(odd ? u01 : u00);
            af[3] = __float_as_uint(odd ? u11 : u10);
#pragma unroll
            for (int nt = 0; nt < 8; nt++) {
                int d = nt * 8 + lr;
                unsigned bf[2];
                bf[0] = __float_as_uint(Vs[(ks * 8 + lc) * VP + d]);
                bf[1] = __float_as_uint(Vs[(ks * 8 + lc + 4) * VP + d]);
                mma_tf32(o[nt], af, bf);
            }
        }
    }

    {
        float li0 = 1.0f / l0, li1 = 1.0f / l1;
        int gq0 = q0 + r0, gq1 = q0 + r1;
#pragma unroll
        for (int nt = 0; nt < 8; nt++) {
            int d = h * DK + nt * 8 + 2 * lc;
            *(float2*)(g_ctx + (size_t)(b * SQ + gq0) * DMODEL + d) =
                make_float2(o[nt][0] * li0, o[nt][1] * li0);
            *(float2*)(g_ctx + (size_t)(b * SQ + gq1) * DMODEL + d) =
                make_float2(o[nt][2] * li1, o[nt][3] * li1);
        }
    }
}

// ---------------------------------------------------------------------------
extern "C" void kernel_launch(void* const* d_in, const int* in_sizes, int n_in,
                              void* d_out, int out_size) {
    (void)in_sizes; (void)n_in; (void)out_size;
    const float* hidden = (const float*)d_in[0];
    const float* mask   = (const float*)d_in[1];
    const float* Wqkv   = (const float*)d_in[2];
    const float* Wo     = (const float*)d_in[3];
    const float* emb    = (const float*)d_in[4];
    float* out = (float*)d_out;

    bias_kernel<<<16, 256>>>(emb);
    flag_init_kernel<<<1, 1>>>();
    mask_check_kernel<<<2048, 256>>>(mask);

    gemm_tc<3072, 0><<<dim3(24, 32), 256>>>(hidden, Wqkv, nullptr);

    const int smem_bytes = (BQ * QP + BKV * KP + BKV * VP + 192) * 4;
    cudaFuncSetAttribute(attn_tc, cudaFuncAttributeMaxDynamicSharedMemorySize,
                         smem_bytes);
    attn_tc<<<dim3(SQ / BQ, NH, BATCH), 256, smem_bytes>>>(mask);

    gemm_tc<1024, 1><<<dim3(8, 32), 256>>>(nullptr, Wo, out);
}